// round 4
// baseline (speedup 1.0000x reference)
#include <cuda_runtime.h>

// TSModel: 2-layer LSTM recurrence (layer0: 1->64, layer1: 64->1 fed c0;
// output = c1 per step). B=2048 rows, T=1024 sequential steps.
//
// R3 design: persistent fp32 kernel, 128 CTAs x 256 threads (8 warps),
// RPW=2 rows/warp -> 2 warps per SMSP to hide LDS/SHFL/MUFU latency.
// Matvec uses sm_103a packed fma.rn.f32x2 (2 FMAs per issue slot),
// gate-interleaved weight layout for LDS.128 weight loads, and duplicated
// (h,h) hidden-state storage so the broadcast operand loads pre-packed.

#define UNITS 64
#define TSTEPS 1024
#define BATCH 2048
#define RPW 2                               // rows per warp
#define WARPS_PER_CTA 8
#define ROWS_PER_CTA (RPW * WARPS_PER_CTA)  // 16
#define NCTA (BATCH / ROWS_PER_CTA)         // 128
// Wp: 64 rows x 256 floats (64KB). hdup: 16 rows x 64 ull (8KB).
#define SMEM_FLOATS (64 * 256 + ROWS_PER_CTA * 64 * 2)
#define SMEM_BYTES (SMEM_FLOATS * (int)sizeof(float))

typedef unsigned long long ull;

__device__ __forceinline__ ull ffma2(ull a, ull b, ull c) {
    ull d;
    asm("fma.rn.f32x2 %0, %1, %2, %3;" : "=l"(d) : "l"(a), "l"(b), "l"(c));
    return d;
}
__device__ __forceinline__ ull pack2(float x, float y) {
    ull d;
    asm("mov.b64 %0, {%1, %2};" : "=l"(d) : "f"(x), "f"(y));
    return d;
}
__device__ __forceinline__ ull dup2(float x) {
    ull d;
    asm("mov.b64 %0, {%1, %1};" : "=l"(d) : "f"(x));
    return d;
}
__device__ __forceinline__ float2 unpack2(ull v) {
    float2 f;
    asm("mov.b64 {%0, %1}, %2;" : "=f"(f.x), "=f"(f.y) : "l"(v));
    return f;
}

__device__ __forceinline__ float sigf(float x) {
    return __fdividef(1.0f, 1.0f + __expf(-x));
}
__device__ __forceinline__ float tanhfast(float x) {
    return 2.0f * __fdividef(1.0f, 1.0f + __expf(-2.0f * x)) - 1.0f;
}

__global__ void __launch_bounds__(WARPS_PER_CTA * 32)
lstm_kernel(const float* __restrict__ input,
            const float* __restrict__ W_ih0, const float* __restrict__ W_hh0,
            const float* __restrict__ b_ih0, const float* __restrict__ b_hh0,
            const float* __restrict__ W_ih1, const float* __restrict__ W_hh1,
            const float* __restrict__ b_ih1, const float* __restrict__ b_hh1,
            float* __restrict__ out)
{
    extern __shared__ float smem[];
    float* Wp = smem;                       // [64][256] gate-interleaved, see below
    ull*   hd = (ull*)(smem + 64 * 256);    // [16 rows][64]  (h[k],h[k]) packed

    const int tid  = threadIdx.x;
    const int wid  = tid >> 5;
    const int lane = tid & 31;

    // Wp[k][j*8 + q*2 + s] = W_hh0[64q + 2j + s][k]
    // -> lane j reads its 8 weights for step-k as two contiguous float4s.
    for (int idx = tid; idx < 64 * 256; idx += blockDim.x) {
        int k = idx >> 8, c = idx & 255;
        int j = c >> 3, rem = c & 7;
        int q = rem >> 1, s = rem & 1;
        int g = 64 * q + 2 * j + s;
        Wp[idx] = W_hh0[g * UNITS + k];
    }
    for (int i = tid; i < ROWS_PER_CTA * 64; i += blockDim.x) hd[i] = 0ULL;
    __syncthreads();

    // Per-lane constants (lane j owns units 2j, 2j+1 of each gate group).
    ull bias2[4], wih2[4];
    float2 w1[4];
    float  wh1r[4], b1r[4];
#pragma unroll
    for (int q = 0; q < 4; q++) {
        int g = 64 * q + 2 * lane;
        bias2[q] = pack2(b_ih0[g] + b_hh0[g], b_ih0[g + 1] + b_hh0[g + 1]);
        wih2[q]  = pack2(W_ih0[g], W_ih0[g + 1]);
        w1[q]    = make_float2(W_ih1[q * UNITS + 2 * lane],
                               W_ih1[q * UNITS + 2 * lane + 1]);
        wh1r[q]  = W_hh1[q];
        b1r[q]   = b_ih1[q] + b_hh1[q];
    }

    const int row0 = blockIdx.x * ROWS_PER_CTA + wid * RPW;
    ull* hdw = hd + (wid * RPW) * 64;             // this warp's h rows
    const ulonglong2* Wp2 = (const ulonglong2*)Wp; // 64 ulonglong2 per k-row

    float c0[RPW][2] = {};
    float h1[RPW] = {}, c1[RPW] = {};

    float xcur[RPW], xnxt[RPW];
#pragma unroll
    for (int r = 0; r < RPW; r++) xcur[r] = input[(row0 + r) * TSTEPS + lane];

    for (int t = 0; t < TSTEPS; t++) {
        const int tm = t & 31;
        if (tm == 0) {
            const int tn = t + 32;
#pragma unroll
            for (int r = 0; r < RPW; r++)
                xnxt[r] = (tn < TSTEPS) ? input[(row0 + r) * TSTEPS + tn + lane] : 0.0f;
        }

        // ---- gates init: bias + x_t * W_ih0 (packed) ----
        ull acc[RPW][4];
#pragma unroll
        for (int r = 0; r < RPW; r++) {
            ull xv2 = dup2(__shfl_sync(0xffffffffu, xcur[r], tm));
#pragma unroll
            for (int q = 0; q < 4; q++)
                acc[r][q] = ffma2(xv2, wih2[q], bias2[q]);
        }
        __syncwarp();   // h writes from step t-1 visible

        // ---- matvec: 32 FFMA2 + 4 LDS.128 + 4 LDS.64 per k2 ----
#pragma unroll 8
        for (int k2 = 0; k2 < 32; k2++) {
            ulonglong2 wA0 = Wp2[(2 * k2)     * 64 + 2 * lane];
            ulonglong2 wA1 = Wp2[(2 * k2)     * 64 + 2 * lane + 1];
            ulonglong2 wB0 = Wp2[(2 * k2 + 1) * 64 + 2 * lane];
            ulonglong2 wB1 = Wp2[(2 * k2 + 1) * 64 + 2 * lane + 1];
#pragma unroll
            for (int r = 0; r < RPW; r++) {
                ull hA = hdw[r * 64 + 2 * k2];      // (h[2k2],h[2k2]) broadcast
                ull hB = hdw[r * 64 + 2 * k2 + 1];
                acc[r][0] = ffma2(hA, wA0.x, acc[r][0]);
                acc[r][1] = ffma2(hA, wA0.y, acc[r][1]);
                acc[r][2] = ffma2(hA, wA1.x, acc[r][2]);
                acc[r][3] = ffma2(hA, wA1.y, acc[r][3]);
                acc[r][0] = ffma2(hB, wB0.x, acc[r][0]);
                acc[r][1] = ffma2(hB, wB0.y, acc[r][1]);
                acc[r][2] = ffma2(hB, wB1.x, acc[r][2]);
                acc[r][3] = ffma2(hB, wB1.y, acc[r][3]);
            }
        }
        __syncwarp();   // all reads of h done before rewriting

        // ---- layer-0 elementwise + layer-1 partial dots ----
        float p[RPW][4];
#pragma unroll
        for (int r = 0; r < RPW; r++) {
            float2 ai = unpack2(acc[r][0]);
            float2 af = unpack2(acc[r][1]);
            float2 ag = unpack2(acc[r][2]);
            float2 ao = unpack2(acc[r][3]);
            float ix = sigf(ai.x),     iy = sigf(ai.y);
            float fx = sigf(af.x),     fy = sigf(af.y);
            float gx = tanhfast(ag.x), gy = tanhfast(ag.y);
            float ox = sigf(ao.x),     oy = sigf(ao.y);
            float cnx = fmaf(fx, c0[r][0], ix * gx);
            float cny = fmaf(fy, c0[r][1], iy * gy);
            c0[r][0] = cnx; c0[r][1] = cny;
            float hnx = ox * tanhfast(cnx);
            float hny = oy * tanhfast(cny);
            hdw[r * 64 + 2 * lane]     = dup2(hnx);
            hdw[r * 64 + 2 * lane + 1] = dup2(hny);
            // layer 1 input is the CELL state c0_new (reference quirk)
#pragma unroll
            for (int q = 0; q < 4; q++)
                p[r][q] = fmaf(cnx, w1[q].x, cny * w1[q].y);
        }

        // ---- butterfly reduce the RPW*4 layer-1 gate sums ----
#pragma unroll
        for (int s = 16; s > 0; s >>= 1) {
#pragma unroll
            for (int r = 0; r < RPW; r++)
#pragma unroll
                for (int q = 0; q < 4; q++)
                    p[r][q] += __shfl_xor_sync(0xffffffffu, p[r][q], s);
        }

        // ---- layer-1 elementwise (replicated across lanes) ----
#pragma unroll
        for (int r = 0; r < RPW; r++) {
            float i1 = sigf(fmaf(wh1r[0], h1[r], p[r][0] + b1r[0]));
            float f1 = sigf(fmaf(wh1r[1], h1[r], p[r][1] + b1r[1]));
            float g1 = tanhfast(fmaf(wh1r[2], h1[r], p[r][2] + b1r[2]));
            float o1 = sigf(fmaf(wh1r[3], h1[r], p[r][3] + b1r[3]));
            float c1n = fmaf(f1, c1[r], i1 * g1);
            c1[r] = c1n;
            h1[r] = o1 * tanhfast(c1n);
        }

        {
            float ov = (lane == 1) ? c1[1] : c1[0];
            if (lane < RPW) out[(row0 + lane) * TSTEPS + t] = ov;
        }

        if (tm == 31) {
#pragma unroll
            for (int r = 0; r < RPW; r++) xcur[r] = xnxt[r];
        }
    }
}

extern "C" void kernel_launch(void* const* d_in, const int* in_sizes, int n_in,
                              void* d_out, int out_size) {
    const float* input = (const float*)d_in[0];
    const float* W_ih0 = (const float*)d_in[1];
    const float* W_hh0 = (const float*)d_in[2];
    const float* b_ih0 = (const float*)d_in[3];
    const float* b_hh0 = (const float*)d_in[4];
    const float* W_ih1 = (const float*)d_in[5];
    const float* W_hh1 = (const float*)d_in[6];
    const float* b_ih1 = (const float*)d_in[7];
    const float* b_hh1 = (const float*)d_in[8];
    float* out = (float*)d_out;

    cudaFuncSetAttribute(lstm_kernel,
                         cudaFuncAttributeMaxDynamicSharedMemorySize, SMEM_BYTES);
    lstm_kernel<<<NCTA, WARPS_PER_CTA * 32, SMEM_BYTES>>>(
        input, W_ih0, W_hh0, b_ih0, b_hh0, W_ih1, W_hh1, b_ih1, b_hh1, out);
}

// round 5
// speedup vs baseline: 1.6352x; 1.6352x over previous
#include <cuda_runtime.h>

// TSModel 2-layer LSTM (layer0: 1->64; layer1: 64->1 fed c0; out = c1).
// B=2048 rows, T=1024 steps.
//
// R4: register-resident weights (persistent-RNN style).
// 128 CTAs x 256 threads, 16 rows/CTA. Thread g (=tid) owns gate output
// g = 64q+u and holds W_hh0[g][0:64] in 32 packed f32x2 registers.
// Per step:
//   phase1: every thread computes gate g for all 16 rows (h via uniform
//           SMEM broadcast loads, fma.rn.f32x2) -> gbuf.     [sync]
//   phase2: thread (u, 4 rows) does the layer-0 cell update (c0 in regs),
//           writes h -> hbuf and c0_new -> cbuf.             [sync]
//   phase3 (threads 0..63): layer-1 dot over c0_new + tiny recurrence
//           (h1,c1 replicated in the 4 lanes of each row group), write out.
// Weight SMEM traffic: zero. Only h/gate exchange moves through SMEM.

#define UNITS   64
#define TSTEPS  1024
#define ROWS    16
#define NCTA    128
#define NTHREADS 256

typedef unsigned long long ull;

__device__ __forceinline__ ull ffma2(ull a, ull b, ull c) {
    ull d;
    asm("fma.rn.f32x2 %0, %1, %2, %3;" : "=l"(d) : "l"(a), "l"(b), "l"(c));
    return d;
}
__device__ __forceinline__ ull pack2(float x, float y) {
    ull d;
    asm("mov.b64 %0, {%1, %2};" : "=l"(d) : "f"(x), "f"(y));
    return d;
}
__device__ __forceinline__ float2 unpack2(ull v) {
    float2 f;
    asm("mov.b64 {%0, %1}, %2;" : "=f"(f.x), "=f"(f.y) : "l"(v));
    return f;
}
__device__ __forceinline__ float sigf(float x) {
    return __fdividef(1.0f, 1.0f + __expf(-x));
}
__device__ __forceinline__ float tanhfast(float x) {
    return 2.0f * __fdividef(1.0f, 1.0f + __expf(-2.0f * x)) - 1.0f;
}

__global__ void __launch_bounds__(NTHREADS, 1)
lstm_kernel(const float* __restrict__ input,
            const float* __restrict__ W_ih0, const float* __restrict__ W_hh0,
            const float* __restrict__ b_ih0, const float* __restrict__ b_hh0,
            const float* __restrict__ W_ih1, const float* __restrict__ W_hh1,
            const float* __restrict__ b_ih1, const float* __restrict__ b_hh1,
            float* __restrict__ out)
{
    __shared__ __align__(16) float hbuf[ROWS][UNITS];   // h0 state
    __shared__ __align__(16) float gbuf[ROWS][256];     // layer-0 gate exchange
    __shared__ __align__(16) float cbuf[ROWS][68];      // c0_new (padded rows)
    __shared__ __align__(16) float xtile[ROWS][64];     // staged input
    __shared__ __align__(16) float W1s[4][68];          // W_ih1 (padded rows)

    const int tid = threadIdx.x;
    const int g   = tid;                 // owned gate output (0..255)
    const int row0 = blockIdx.x * ROWS;

    // ---- one-time init ----
    // W_hh0 row for gate g -> 32 packed f32x2 regs (pairs along k).
    ull wreg[32];
    {
        const ulonglong2* wp = (const ulonglong2*)(W_hh0 + g * UNITS);
#pragma unroll
        for (int m = 0; m < 16; m++) {
            ulonglong2 v = wp[m];
            wreg[2 * m]     = v.x;
            wreg[2 * m + 1] = v.y;
        }
    }
    const float wihg = W_ih0[g];
    const float bsum = b_ih0[g] + b_hh0[g];

    float wh1a[4], b1a[4];
#pragma unroll
    for (int q = 0; q < 4; q++) { wh1a[q] = W_hh1[q]; b1a[q] = b_ih1[q] + b_hh1[q]; }

    if (tid < 4 * UNITS) W1s[tid >> 6][tid & 63] = W_ih1[tid];
    {
        float* hb = &hbuf[0][0];
        for (int i = tid; i < ROWS * UNITS; i += NTHREADS) hb[i] = 0.0f;
    }

    // phase-2 identity: thread handles unit u for rows rb, rb+4, rb+8, rb+12
    const int u  = tid & 63;
    const int rb = tid >> 6;
    float c0s[4] = {0.f, 0.f, 0.f, 0.f};

    // phase-3 identity (threads 0..63): (row r3, gate q3); h1/c1 replicated x4
    const int r3 = tid >> 2, q3 = tid & 3;
    float h1s = 0.f, c1s = 0.f;

    __syncthreads();

    for (int t = 0; t < TSTEPS; t++) {
        const int tm = t & 63;
        if (tm == 0) {
            // stage 64 timesteps of input for the CTA's 16 rows (coalesced)
#pragma unroll
            for (int i = 0; i < 4; i++) {
                int lin = tid + NTHREADS * i;
                int rr = lin >> 6, cc = lin & 63;
                xtile[rr][cc] = input[(row0 + rr) * TSTEPS + t + cc];
            }
            __syncthreads();
        }

        // ---- phase 1: gate g for all 16 rows (register weights) ----
#pragma unroll 4
        for (int r = 0; r < ROWS; r++) {
            const ulonglong2* hv = (const ulonglong2*)hbuf[r];  // uniform bcast
            float xv = xtile[r][tm];
            ull acc_a = pack2(fmaf(xv, wihg, bsum), 0.0f);
            ull acc_b = 0ULL;  // (0.f, 0.f)
#pragma unroll
            for (int m = 0; m < 16; m++) {
                ulonglong2 h2 = hv[m];             // (h4m,h4m+1),(h4m+2,h4m+3)
                acc_a = ffma2(h2.x, wreg[2 * m],     acc_a);
                acc_b = ffma2(h2.y, wreg[2 * m + 1], acc_b);
            }
            float2 fa = unpack2(acc_a), fb = unpack2(acc_b);
            gbuf[r][g] = (fa.x + fb.x) + (fa.y + fb.y);
        }
        __syncthreads();   // S1: gates ready

        // ---- phase 2: layer-0 cell update for (u, 4 rows) ----
#pragma unroll
        for (int j = 0; j < 4; j++) {
            int r = rb + 4 * j;
            float iv = sigf(gbuf[r][u]);
            float fv = sigf(gbuf[r][64 + u]);
            float gv = tanhfast(gbuf[r][128 + u]);
            float ov = sigf(gbuf[r][192 + u]);
            float c  = fmaf(fv, c0s[j], iv * gv);
            c0s[j] = c;
            hbuf[r][u] = ov * tanhfast(c);
            cbuf[r][u] = c;      // layer-1 input is the CELL state (ref quirk)
        }
        __syncthreads();   // S2: h and c0_new ready

        // ---- phase 3 (threads 0..63): layer 1 ----
        if (tid < 64) {
            const ulonglong2* cv = (const ulonglong2*)cbuf[r3];
            const ulonglong2* wv = (const ulonglong2*)W1s[q3];
            ull pa = 0ULL, pb = 0ULL;
#pragma unroll
            for (int m = 0; m < 16; m++) {
                ulonglong2 c2 = cv[m], w2 = wv[m];
                pa = ffma2(c2.x, w2.x, pa);
                pb = ffma2(c2.y, w2.y, pb);
            }
            float2 fa = unpack2(pa), fb = unpack2(pb);
            float pre = (fa.x + fb.x) + (fa.y + fb.y)
                      + b1a[q3] + wh1a[q3] * h1s;
            float act = (q3 == 2) ? tanhfast(pre) : sigf(pre);

            // gather the 4 gate values within each 4-lane row group
            float a1 = __shfl_xor_sync(0xffffffffu, act, 1);
            float gA = (q3 & 1) ? a1 : act;    // gate[q & ~1]
            float gB = (q3 & 1) ? act : a1;    // gate[q | 1]
            float cA = __shfl_xor_sync(0xffffffffu, gA, 2);
            float cB = __shfl_xor_sync(0xffffffffu, gB, 2);
            float i1, f1, g1, o1v;
            if (q3 < 2) { i1 = gA; f1 = gB; g1 = cA; o1v = cB; }
            else        { i1 = cA; f1 = cB; g1 = gA; o1v = gB; }

            float c1n = fmaf(f1, c1s, i1 * g1);
            c1s = c1n;
            h1s = o1v * tanhfast(c1n);
            if (q3 == 0) out[(row0 + r3) * TSTEPS + t] = c1n;
        }
    }
}

extern "C" void kernel_launch(void* const* d_in, const int* in_sizes, int n_in,
                              void* d_out, int out_size) {
    const float* input = (const float*)d_in[0];
    const float* W_ih0 = (const float*)d_in[1];
    const float* W_hh0 = (const float*)d_in[2];
    const float* b_ih0 = (const float*)d_in[3];
    const float* b_hh0 = (const float*)d_in[4];
    const float* W_ih1 = (const float*)d_in[5];
    const float* W_hh1 = (const float*)d_in[6];
    const float* b_ih1 = (const float*)d_in[7];
    const float* b_hh1 = (const float*)d_in[8];
    float* out = (float*)d_out;

    lstm_kernel<<<NCTA, NTHREADS>>>(
        input, W_ih0, W_hh0, b_ih0, b_hh0, W_ih1, W_hh1, b_ih1, b_hh1, out);
}

// round 7
// speedup vs baseline: 1.7539x; 1.0726x over previous
#include <cuda_runtime.h>

// TSModel 2-layer LSTM (layer0: 1->64; layer1: 64->1 fed c0; out = c1 per step).
// B=2048 rows, T=1024 steps.
//
// R6 = R5 with the matvec/dot trip-count bug fixed (m<16, covering all 64
// hidden units; R5's m<8 dropped half the recurrence matrix).
// Design: register-resident weights, 128 CTAs x 512 threads (4 warps/SMSP).
// Thread (g = tid&255, rg = tid>>8) holds W_hh0[g][0:64] in 32 packed f32x2
// regs and computes gate g for its 8 rows via LDS.128 h broadcasts.
//   P1 matvec -> gbuf | bar | P2 cell update -> h,c | bar | L1 on tid<64.

#define UNITS   64
#define TSTEPS  1024
#define ROWS    16
#define NCTA    128
#define NT      512

typedef unsigned long long ull;

__device__ __forceinline__ ull ffma2(ull a, ull b, ull c) {
    ull d;
    asm("fma.rn.f32x2 %0, %1, %2, %3;" : "=l"(d) : "l"(a), "l"(b), "l"(c));
    return d;
}
__device__ __forceinline__ ull pack2(float x, float y) {
    ull d;
    asm("mov.b64 %0, {%1, %2};" : "=l"(d) : "f"(x), "f"(y));
    return d;
}
__device__ __forceinline__ float2 unpack2(ull v) {
    float2 f;
    asm("mov.b64 {%0, %1}, %2;" : "=f"(f.x), "=f"(f.y) : "l"(v));
    return f;
}
__device__ __forceinline__ float sigf(float x) {
    return __fdividef(1.0f, 1.0f + __expf(-x));
}
__device__ __forceinline__ float tanhfast(float x) {
    return 2.0f * __fdividef(1.0f, 1.0f + __expf(-2.0f * x)) - 1.0f;
}

__global__ void __launch_bounds__(NT, 1)
lstm_kernel(const float* __restrict__ input,
            const float* __restrict__ W_ih0, const float* __restrict__ W_hh0,
            const float* __restrict__ b_ih0, const float* __restrict__ b_hh0,
            const float* __restrict__ W_ih1, const float* __restrict__ W_hh1,
            const float* __restrict__ b_ih1, const float* __restrict__ b_hh1,
            float* __restrict__ out)
{
    __shared__ __align__(16) float gbuf[ROWS][256];   // gate exchange (16 KB)
    __shared__ __align__(16) float hbuf[ROWS][UNITS]; // h0 state
    __shared__ __align__(16) float cbuf[ROWS][68];    // c0_new (padded rows)
    __shared__ __align__(16) float xtile[ROWS][64];   // staged input
    __shared__ __align__(16) float W1s[4][68];        // W_ih1 (padded rows)

    const int tid = threadIdx.x;
    const int g   = tid & 255;      // P1: owned gate output
    const int rg  = tid >> 8;       // P1: row group (rows 8rg..8rg+7)
    const int row0 = blockIdx.x * ROWS;

    // ---- one-time init ----
    ull wreg[32];                   // W_hh0[g][0:64] as packed f32x2 pairs
    {
        const ulonglong2* wp = (const ulonglong2*)(W_hh0 + g * UNITS);
#pragma unroll
        for (int m = 0; m < 16; m++) {
            ulonglong2 v = wp[m];
            wreg[2 * m]     = v.x;
            wreg[2 * m + 1] = v.y;
        }
    }
    const float wihg = W_ih0[g];
    const float bsum = b_ih0[g] + b_hh0[g];

    float wh1a[4], b1a[4];
#pragma unroll
    for (int q = 0; q < 4; q++) { wh1a[q] = W_hh1[q]; b1a[q] = b_ih1[q] + b_hh1[q]; }
    if (tid < 4 * UNITS) W1s[tid >> 6][tid & 63] = W_ih1[tid];
    {
        float* hb = &hbuf[0][0];
        for (int i = tid; i < ROWS * UNITS; i += NT) hb[i] = 0.0f;
    }

    // P2 identity: unit u2, rows {rs, rs+8}
    const int u2 = tid & 63;
    const int rs = tid >> 6;        // 0..7
    float c0s[2] = {0.f, 0.f};

    // layer-1 identity (tid<64): row r1, gate q1; h1/c1 replicated in 4 lanes
    const int r1 = tid >> 2, q1 = tid & 3;
    float h1s = 0.f, c1s = 0.f;

    __syncthreads();

    for (int t = 0; t < TSTEPS; t++) {
        const int tm = t & 63;
        if (tm == 0) {
            // stage 64 timesteps for the CTA's 16 rows (coalesced)
#pragma unroll
            for (int i = 0; i < 2; i++) {
                int lin = tid + NT * i;
                int rr = lin >> 6, cc = lin & 63;
                xtile[rr][cc] = input[(row0 + rr) * TSTEPS + t + cc];
            }
            __syncthreads();
        }

        // ---- P1: gate g for 8 rows; register weights, LDS.128 h broadcast ----
#pragma unroll 2
        for (int rr = 0; rr < 8; rr++) {
            const int r = 8 * rg + rr;
            const ulonglong2* hv = (const ulonglong2*)hbuf[r];  // uniform bcast
            float xv = xtile[r][tm];
            ull accA = pack2(fmaf(xv, wihg, bsum), 0.0f);
            ull accB = 0ULL;
#pragma unroll
            for (int m = 0; m < 16; m++) {       // 16 x 16B = all 64 h values
                ulonglong2 h2 = hv[m];           // floats [4m .. 4m+4)
                accA = ffma2(h2.x, wreg[2 * m],     accA);
                accB = ffma2(h2.y, wreg[2 * m + 1], accB);
            }
            float2 fa = unpack2(accA), fb = unpack2(accB);
            gbuf[r][g] = (fa.x + fb.x) + (fa.y + fb.y);
        }
        __syncthreads();   // S1: gates ready

        // ---- P2: layer-0 cell update for (u2, rows rs, rs+8) ----
#pragma unroll
        for (int j = 0; j < 2; j++) {
            const int r = rs + 8 * j;
            float iv = sigf(gbuf[r][u2]);
            float fv = sigf(gbuf[r][64 + u2]);
            float gv = tanhfast(gbuf[r][128 + u2]);
            float ov = sigf(gbuf[r][192 + u2]);
            float c  = fmaf(fv, c0s[j], iv * gv);
            c0s[j] = c;
            hbuf[r][u2] = ov * tanhfast(c);
            cbuf[r][u2] = c;   // layer-1 input is the CELL state (ref quirk)
        }
        __syncthreads();   // S2: h, c0_new ready

        // ---- layer 1 (threads 0..63); other warps run ahead to next P1 ----
        if (tid < 64) {
            const ulonglong2* cv = (const ulonglong2*)cbuf[r1];
            const ulonglong2* wv = (const ulonglong2*)W1s[q1];
            ull pa = 0ULL, pb = 0ULL;
#pragma unroll
            for (int m = 0; m < 16; m++) {       // full 64-element dot
                ulonglong2 c2 = cv[m], w2 = wv[m];
                pa = ffma2(c2.x, w2.x, pa);
                pb = ffma2(c2.y, w2.y, pb);
            }
            float2 fa = unpack2(pa), fb = unpack2(pb);
            float pre = (fa.x + fb.x) + (fa.y + fb.y)
                      + b1a[q1] + wh1a[q1] * h1s;
            float act = (q1 == 2) ? tanhfast(pre) : sigf(pre);

            // gather the 4 gate values within each 4-lane row group
            float a1 = __shfl_xor_sync(0xffffffffu, act, 1);
            float gA = (q1 & 1) ? a1 : act;    // gate[q & ~1]
            float gB = (q1 & 1) ? act : a1;    // gate[q | 1]
            float cA = __shfl_xor_sync(0xffffffffu, gA, 2);
            float cB = __shfl_xor_sync(0xffffffffu, gB, 2);
            float i1, f1, g1, o1v;
            if (q1 < 2) { i1 = gA; f1 = gB; g1 = cA; o1v = cB; }
            else        { i1 = cA; f1 = cB; g1 = gA; o1v = gB; }

            float c1n = fmaf(f1, c1s, i1 * g1);
            c1s = c1n;
            h1s = o1v * tanhfast(c1n);
            if (q1 == 0) out[(row0 + r1) * TSTEPS + t] = c1n;
        }
    }
}

extern "C" void kernel_launch(void* const* d_in, const int* in_sizes, int n_in,
                              void* d_out, int out_size) {
    const float* input = (const float*)d_in[0];
    const float* W_ih0 = (const float*)d_in[1];
    const float* W_hh0 = (const float*)d_in[2];
    const float* b_ih0 = (const float*)d_in[3];
    const float* b_hh0 = (const float*)d_in[4];
    const float* W_ih1 = (const float*)d_in[5];
    const float* W_hh1 = (const float*)d_in[6];
    const float* b_ih1 = (const float*)d_in[7];
    const float* b_hh1 = (const float*)d_in[8];
    float* out = (float*)d_out;

    lstm_kernel<<<NCTA, NT>>>(
        input, W_ih0, W_hh0, b_ih0, b_hh0, W_ih1, W_hh1, b_ih1, b_hh1, out);
}

// round 8
// speedup vs baseline: 2.1664x; 1.2352x over previous
#include <cuda_runtime.h>

// TSModel 2-layer LSTM (layer0: 1->64; layer1: 64->1 fed c0; out = c1/step).
// B=2048 rows, T=1024 steps.
//
// R7: halve the h-broadcast crossbar traffic (the R6 wall, L1=69.5%).
// 256 CTAs x 256 threads (2 CTAs/SM), 8 rows/CTA.
// Warp (q = wid>>1, kh = wid&1): gate-type q, K-half kh. Lane l owns the
// f32x2-adjacent gate pair (64q+2l, 64q+2l+1) with weights for K-slice
// [32kh,32kh+32) in registers (32 ull). h broadcast: 8 LDS.128 per row
// (vs 16 in R6). K-halves are partial sums combined in P2 via gbuf.

#define UNITS   64
#define TSTEPS  1024
#define ROWS    8
#define NCTA    256
#define NT      256

typedef unsigned long long ull;

__device__ __forceinline__ ull ffma2(ull a, ull b, ull c) {
    ull d;
    asm("fma.rn.f32x2 %0, %1, %2, %3;" : "=l"(d) : "l"(a), "l"(b), "l"(c));
    return d;
}
__device__ __forceinline__ ull pack2(float x, float y) {
    ull d;
    asm("mov.b64 %0, {%1, %2};" : "=l"(d) : "f"(x), "f"(y));
    return d;
}
__device__ __forceinline__ float2 unpack2(ull v) {
    float2 f;
    asm("mov.b64 {%0, %1}, %2;" : "=f"(f.x), "=f"(f.y) : "l"(v));
    return f;
}
__device__ __forceinline__ float sigf(float x) {
    return __fdividef(1.0f, 1.0f + __expf(-x));
}
__device__ __forceinline__ float tanhfast(float x) {
    return 2.0f * __fdividef(1.0f, 1.0f + __expf(-2.0f * x)) - 1.0f;
}

__global__ void __launch_bounds__(NT, 2)
lstm_kernel(const float* __restrict__ input,
            const float* __restrict__ W_ih0, const float* __restrict__ W_hh0,
            const float* __restrict__ b_ih0, const float* __restrict__ b_hh0,
            const float* __restrict__ W_ih1, const float* __restrict__ W_hh1,
            const float* __restrict__ b_ih1, const float* __restrict__ b_hh1,
            float* __restrict__ out)
{
    __shared__ __align__(16) float gbuf[ROWS][2][4][UNITS]; // partials (16 KB)
    __shared__ __align__(16) float hbuf[ROWS][UNITS];       // h0 state
    __shared__ __align__(16) float cbuf[ROWS][68];          // c0_new (16B-pad)
    __shared__ __align__(16) float xtile[ROWS][64];         // staged input
    __shared__ __align__(16) float W1s[4][68];              // W_ih1

    const int tid  = threadIdx.x;
    const int wid  = tid >> 5;
    const int lane = tid & 31;
    const int q    = wid >> 1;          // gate type (i,f,g,o)
    const int kh   = wid & 1;           // K-half
    const int row0 = blockIdx.x * ROWS;

    // ---- one-time init ----
    // Lane's gates: gA = 64q+2l, gB = gA+1; K-slice [32kh, 32kh+32).
    const int gA = 64 * q + 2 * lane;
    const int gB = gA + 1;
    ull wregA[16], wregB[16];           // (W[g][2k],W[g][2k+1]) pairs, 32 K
    {
        const ulonglong2* wa = (const ulonglong2*)(W_hh0 + gA * UNITS + 32 * kh);
        const ulonglong2* wb = (const ulonglong2*)(W_hh0 + gB * UNITS + 32 * kh);
#pragma unroll
        for (int m = 0; m < 8; m++) {
            ulonglong2 va = wa[m], vb = wb[m];
            wregA[2 * m] = va.x; wregA[2 * m + 1] = va.y;
            wregB[2 * m] = vb.x; wregB[2 * m + 1] = vb.y;
        }
    }
    // x/bias injected only by the kh==0 warp (K-halves sum in P2).
    const float wihA = (kh == 0) ? W_ih0[gA] : 0.0f;
    const float wihB = (kh == 0) ? W_ih0[gB] : 0.0f;
    const float bsA  = (kh == 0) ? (b_ih0[gA] + b_hh0[gA]) : 0.0f;
    const float bsB  = (kh == 0) ? (b_ih0[gB] + b_hh0[gB]) : 0.0f;

    float wh1a[4], b1a[4];
#pragma unroll
    for (int k = 0; k < 4; k++) { wh1a[k] = W_hh1[k]; b1a[k] = b_ih1[k] + b_hh1[k]; }
    if (tid < 4 * UNITS) W1s[tid >> 6][tid & 63] = W_ih1[tid];
    {
        float* hb = &hbuf[0][0];
        for (int i = tid; i < ROWS * UNITS; i += NT) hb[i] = 0.0f;
    }

    // P2 identity: unit u2, rows {rs, rs+4}
    const int u2 = tid & 63;
    const int rs = tid >> 6;            // 0..3
    float c0s[2] = {0.f, 0.f};

    // layer-1 identity (warp 0): row r1 (0..7), gate q1
    const int r1 = tid >> 2, q1 = tid & 3;
    float h1s = 0.f, c1s = 0.f;

    __syncthreads();

    for (int t = 0; t < TSTEPS; t++) {
        const int tm = t & 63;
        if (tm == 0) {
            // stage 64 timesteps for the CTA's 8 rows (coalesced)
#pragma unroll
            for (int i = 0; i < 2; i++) {
                int lin = tid + NT * i;
                int rr = lin >> 6, cc = lin & 63;
                xtile[rr][cc] = input[(row0 + rr) * TSTEPS + t + cc];
            }
            __syncthreads();
        }

        // ---- P1: 2 gates x 8 rows over K-half; 8 LDS.128 per row ----
#pragma unroll 2
        for (int r = 0; r < ROWS; r++) {
            const ulonglong2* hv = (const ulonglong2*)(hbuf[r] + 32 * kh);
            float xv = xtile[r][tm];
            ull accA = pack2(fmaf(xv, wihA, bsA), 0.0f);
            ull accB = pack2(fmaf(xv, wihB, bsB), 0.0f);
#pragma unroll
            for (int m = 0; m < 8; m++) {        // 8 x 16B = this K-half
                ulonglong2 h2 = hv[m];           // (h,h+1),(h+2,h+3) pairs
                accA = ffma2(h2.x, wregA[2 * m],     accA);
                accB = ffma2(h2.x, wregB[2 * m],     accB);
                accA = ffma2(h2.y, wregA[2 * m + 1], accA);
                accB = ffma2(h2.y, wregB[2 * m + 1], accB);
            }
            float2 fa = unpack2(accA), fb = unpack2(accB);
            *(ull*)&gbuf[r][kh][q][2 * lane] =
                pack2(fa.x + fa.y, fb.x + fb.y);
        }
        __syncthreads();   // S1: partials ready

        // ---- P2: combine K-halves + layer-0 cell update (u2, rows rs,rs+4) ----
#pragma unroll
        for (int j = 0; j < 2; j++) {
            const int r = rs + 4 * j;
            float iv = sigf(gbuf[r][0][0][u2] + gbuf[r][1][0][u2]);
            float fv = sigf(gbuf[r][0][1][u2] + gbuf[r][1][1][u2]);
            float gv = tanhfast(gbuf[r][0][2][u2] + gbuf[r][1][2][u2]);
            float ov = sigf(gbuf[r][0][3][u2] + gbuf[r][1][3][u2]);
            float c  = fmaf(fv, c0s[j], iv * gv);
            c0s[j] = c;
            hbuf[r][u2] = ov * tanhfast(c);
            cbuf[r][u2] = c;   // layer-1 input is the CELL state (ref quirk)
        }
        __syncthreads();   // S2: h, c0_new ready

        // ---- layer 1 (warp 0); other warps run ahead to next P1 ----
        if (tid < 32) {
            const ulonglong2* cv = (const ulonglong2*)cbuf[r1];
            const ulonglong2* wv = (const ulonglong2*)W1s[q1];
            ull pa = 0ULL, pb = 0ULL;
#pragma unroll
            for (int m = 0; m < 16; m++) {       // full 64-element dot
                ulonglong2 c2 = cv[m], w2 = wv[m];
                pa = ffma2(c2.x, w2.x, pa);
                pb = ffma2(c2.y, w2.y, pb);
            }
            float2 fa = unpack2(pa), fb = unpack2(pb);
            float pre = (fa.x + fb.x) + (fa.y + fb.y)
                      + b1a[q1] + wh1a[q1] * h1s;
            float act = (q1 == 2) ? tanhfast(pre) : sigf(pre);

            // gather the 4 gate values within each 4-lane row group
            float a1 = __shfl_xor_sync(0xffffffffu, act, 1);
            float gAv = (q1 & 1) ? a1 : act;    // gate[q & ~1]
            float gBv = (q1 & 1) ? act : a1;    // gate[q | 1]
            float cA = __shfl_xor_sync(0xffffffffu, gAv, 2);
            float cB = __shfl_xor_sync(0xffffffffu, gBv, 2);
            float i1, f1, g1, o1v;
            if (q1 < 2) { i1 = gAv; f1 = gBv; g1 = cA; o1v = cB; }
            else        { i1 = cA; f1 = cB; g1 = gAv; o1v = gBv; }

            float c1n = fmaf(f1, c1s, i1 * g1);
            c1s = c1n;
            h1s = o1v * tanhfast(c1n);
            if (q1 == 0) out[(row0 + r1) * TSTEPS + t] = c1n;
        }
    }
}

extern "C" void kernel_launch(void* const* d_in, const int* in_sizes, int n_in,
                              void* d_out, int out_size) {
    const float* input = (const float*)d_in[0];
    const float* W_ih0 = (const float*)d_in[1];
    const float* W_hh0 = (const float*)d_in[2];
    const float* b_ih0 = (const float*)d_in[3];
    const float* b_hh0 = (const float*)d_in[4];
    const float* W_ih1 = (const float*)d_in[5];
    const float* W_hh1 = (const float*)d_in[6];
    const float* b_ih1 = (const float*)d_in[7];
    const float* b_hh1 = (const float*)d_in[8];
    float* out = (float*)d_out;

    lstm_kernel<<<NCTA, NT>>>(
        input, W_ih0, W_hh0, b_ih0, b_hh0, W_ih1, W_hh1, b_ih1, b_hh1, out);
}

// round 9
// speedup vs baseline: 2.4471x; 1.1296x over previous
#include <cuda_runtime.h>

// TSModel 2-layer LSTM (layer0: 1->64; layer1: 64->1 fed c0; out = c1/step).
// B=2048 rows, T=1024 steps.
//
// R8 = R7 with chip-level load balance fixed: 296 CTAs (=2x148 SMs) x 256
// threads, 7 rows/CTA -> every SM runs exactly 2 CTAs x 7 rows (R7's grid=256
// left 40 SMs half-idle while 108 SMs carried 16 rows).
// Warp (q = wid>>2... ) unchanged from R7: warp (q, kh) owns gate-type q,
// K-half kh; lane l owns gate pair (64q+2l, +1), weights in 32 ull regs;
// h broadcast via LDS.128. P1 -> gbuf | bar | P2 cell update | bar | L1 tail.

#define UNITS   64
#define TSTEPS  1024
#define ROWS    7
#define NCTA    296
#define NT      256
#define NROWS_TOTAL 2048

typedef unsigned long long ull;

__device__ __forceinline__ ull ffma2(ull a, ull b, ull c) {
    ull d;
    asm("fma.rn.f32x2 %0, %1, %2, %3;" : "=l"(d) : "l"(a), "l"(b), "l"(c));
    return d;
}
__device__ __forceinline__ ull pack2(float x, float y) {
    ull d;
    asm("mov.b64 %0, {%1, %2};" : "=l"(d) : "f"(x), "f"(y));
    return d;
}
__device__ __forceinline__ float2 unpack2(ull v) {
    float2 f;
    asm("mov.b64 {%0, %1}, %2;" : "=f"(f.x), "=f"(f.y) : "l"(v));
    return f;
}
__device__ __forceinline__ float sigf(float x) {
    return __fdividef(1.0f, 1.0f + __expf(-x));
}
__device__ __forceinline__ float tanhfast(float x) {
    return 2.0f * __fdividef(1.0f, 1.0f + __expf(-2.0f * x)) - 1.0f;
}

__global__ void __launch_bounds__(NT, 2)
lstm_kernel(const float* __restrict__ input,
            const float* __restrict__ W_ih0, const float* __restrict__ W_hh0,
            const float* __restrict__ b_ih0, const float* __restrict__ b_hh0,
            const float* __restrict__ W_ih1, const float* __restrict__ W_hh1,
            const float* __restrict__ b_ih1, const float* __restrict__ b_hh1,
            float* __restrict__ out)
{
    __shared__ __align__(16) float gbuf[ROWS][2][4][UNITS]; // K-half partials
    __shared__ __align__(16) float hbuf[ROWS][UNITS];       // h0 state
    __shared__ __align__(16) float cbuf[ROWS][68];          // c0_new (padded)
    __shared__ __align__(16) float xtile[ROWS][64];         // staged input
    __shared__ __align__(16) float W1s[4][68];              // W_ih1

    const int row0 = blockIdx.x * ROWS;
    if (row0 >= NROWS_TOTAL) return;    // fully-OOB CTAs free their SM slot

    const int tid  = threadIdx.x;
    const int wid  = tid >> 5;
    const int lane = tid & 31;
    const int q    = wid >> 1;          // gate type (i,f,g,o)
    const int kh   = wid & 1;           // K-half

    // ---- one-time init ----
    const int gA = 64 * q + 2 * lane;   // lane's f32x2-adjacent gate pair
    const int gB = gA + 1;
    ull wregA[16], wregB[16];           // weights for K-slice [32kh,32kh+32)
    {
        const ulonglong2* wa = (const ulonglong2*)(W_hh0 + gA * UNITS + 32 * kh);
        const ulonglong2* wb = (const ulonglong2*)(W_hh0 + gB * UNITS + 32 * kh);
#pragma unroll
        for (int m = 0; m < 8; m++) {
            ulonglong2 va = wa[m], vb = wb[m];
            wregA[2 * m] = va.x; wregA[2 * m + 1] = va.y;
            wregB[2 * m] = vb.x; wregB[2 * m + 1] = vb.y;
        }
    }
    // x/bias injected only by the kh==0 warp (halves summed in P2)
    const float wihA = (kh == 0) ? W_ih0[gA] : 0.0f;
    const float wihB = (kh == 0) ? W_ih0[gB] : 0.0f;
    const float bsA  = (kh == 0) ? (b_ih0[gA] + b_hh0[gA]) : 0.0f;
    const float bsB  = (kh == 0) ? (b_ih0[gB] + b_hh0[gB]) : 0.0f;

    float wh1a[4], b1a[4];
#pragma unroll
    for (int k = 0; k < 4; k++) { wh1a[k] = W_hh1[k]; b1a[k] = b_ih1[k] + b_hh1[k]; }
    if (tid < 4 * UNITS) W1s[tid >> 6][tid & 63] = W_ih1[tid];
    {
        float* hb = &hbuf[0][0];
        for (int i = tid; i < ROWS * UNITS; i += NT) hb[i] = 0.0f;
    }

    // P2 identity: unit u2, rows {rs, rs+4} (row rs+4 valid only for rs<3)
    const int u2 = tid & 63;
    const int rs = tid >> 6;            // 0..3
    float c0s[2] = {0.f, 0.f};

    // layer-1 identity (warp 0): row r1 (0..7, clamp >=7), gate q1
    const int r1 = tid >> 2, q1 = tid & 3;
    const int r1c = (r1 < ROWS) ? r1 : (ROWS - 1);
    float h1s = 0.f, c1s = 0.f;

    __syncthreads();

    for (int t = 0; t < TSTEPS; t++) {
        const int tm = t & 63;
        if (tm == 0) {
            // stage 64 timesteps for the CTA's rows (coalesced; clamp OOB rows)
#pragma unroll
            for (int i = 0; i < 2; i++) {
                int lin = tid + NT * i;
                if (lin < ROWS * 64) {
                    int rr = lin >> 6, cc = lin & 63;
                    int grow = row0 + rr;
                    if (grow > NROWS_TOTAL - 1) grow = NROWS_TOTAL - 1;
                    xtile[rr][cc] = input[grow * TSTEPS + t + cc];
                }
            }
            __syncthreads();
        }

        // ---- P1: 2 gates x 7 rows over this K-half; 8 LDS.128 per row ----
#pragma unroll
        for (int r = 0; r < ROWS; r++) {
            const ulonglong2* hv = (const ulonglong2*)(hbuf[r] + 32 * kh);
            float xv = xtile[r][tm];
            ull accA = pack2(fmaf(xv, wihA, bsA), 0.0f);
            ull accB = pack2(fmaf(xv, wihB, bsB), 0.0f);
#pragma unroll
            for (int m = 0; m < 8; m++) {        // 8 x 16B = this K-half
                ulonglong2 h2 = hv[m];
                accA = ffma2(h2.x, wregA[2 * m],     accA);
                accB = ffma2(h2.x, wregB[2 * m],     accB);
                accA = ffma2(h2.y, wregA[2 * m + 1], accA);
                accB = ffma2(h2.y, wregB[2 * m + 1], accB);
            }
            float2 fa = unpack2(accA), fb = unpack2(accB);
            *(ull*)&gbuf[r][kh][q][2 * lane] = pack2(fa.x + fa.y, fb.x + fb.y);
        }
        __syncthreads();   // S1: partials ready

        // ---- P2: combine K-halves + layer-0 cell update ----
#pragma unroll
        for (int j = 0; j < 2; j++) {
            const int r = rs + 4 * j;
            if (j == 1 && rs >= ROWS - 4) break;   // rows 4..6 only
            float iv = sigf(gbuf[r][0][0][u2] + gbuf[r][1][0][u2]);
            float fv = sigf(gbuf[r][0][1][u2] + gbuf[r][1][1][u2]);
            float gv = tanhfast(gbuf[r][0][2][u2] + gbuf[r][1][2][u2]);
            float ov = sigf(gbuf[r][0][3][u2] + gbuf[r][1][3][u2]);
            float c  = fmaf(fv, c0s[j], iv * gv);
            c0s[j] = c;
            hbuf[r][u2] = ov * tanhfast(c);
            cbuf[r][u2] = c;   // layer-1 input is the CELL state (ref quirk)
        }
        __syncthreads();   // S2: h, c0_new ready

        // ---- layer 1 (warp 0); other warps run ahead to next P1 ----
        if (tid < 32) {
            const ulonglong2* cv = (const ulonglong2*)cbuf[r1c];
            const ulonglong2* wv = (const ulonglong2*)W1s[q1];
            ull pa = 0ULL, pb = 0ULL;
#pragma unroll
            for (int m = 0; m < 16; m++) {       // full 64-element dot
                ulonglong2 c2 = cv[m], w2 = wv[m];
                pa = ffma2(c2.x, w2.x, pa);
                pb = ffma2(c2.y, w2.y, pb);
            }
            float2 fa = unpack2(pa), fb = unpack2(pb);
            float pre = (fa.x + fb.x) + (fa.y + fb.y)
                      + b1a[q1] + wh1a[q1] * h1s;
            float act = (q1 == 2) ? tanhfast(pre) : sigf(pre);

            // gather the 4 gate values within each 4-lane row group
            float a1 = __shfl_xor_sync(0xffffffffu, act, 1);
            float gAv = (q1 & 1) ? a1 : act;    // gate[q & ~1]
            float gBv = (q1 & 1) ? act : a1;    // gate[q | 1]
            float cA = __shfl_xor_sync(0xffffffffu, gAv, 2);
            float cB = __shfl_xor_sync(0xffffffffu, gBv, 2);
            float i1, f1, g1, o1v;
            if (q1 < 2) { i1 = gAv; f1 = gBv; g1 = cA; o1v = cB; }
            else        { i1 = cA; f1 = cB; g1 = gAv; o1v = gBv; }

            float c1n = fmaf(f1, c1s, i1 * g1);
            c1s = c1n;
            h1s = o1v * tanhfast(c1n);
            if (q1 == 0 && r1 < ROWS && (row0 + r1) < NROWS_TOTAL)
                out[(row0 + r1) * TSTEPS + t] = c1n;
        }
    }
}

extern "C" void kernel_launch(void* const* d_in, const int* in_sizes, int n_in,
                              void* d_out, int out_size) {
    const float* input = (const float*)d_in[0];
    const float* W_ih0 = (const float*)d_in[1];
    const float* W_hh0 = (const float*)d_in[2];
    const float* b_ih0 = (const float*)d_in[3];
    const float* b_hh0 = (const float*)d_in[4];
    const float* W_ih1 = (const float*)d_in[5];
    const float* W_hh1 = (const float*)d_in[6];
    const float* b_ih1 = (const float*)d_in[7];
    const float* b_hh1 = (const float*)d_in[8];
    float* out = (float*)d_out;

    lstm_kernel<<<NCTA, NT>>>(
        input, W_ih0, W_hh0, b_ih0, b_hh0, W_ih1, W_hh1, b_ih1, b_hh1, out);
}